// round 9
// baseline (speedup 1.0000x reference)
#include <cuda_runtime.h>
#include <cuda_fp16.h>
#include <cstdint>

// ---------------------------------------------------------------------------
// S=8 streams, I=64 mod dims, M=256 features, N=16384 batch.
// Collapsed math:  z_g[n,s,m] = sum_i C_g[s,m,i]*mod[n,s,i] + Bias[s,g,m]
//   C_g  = alpha_g * (W_g[:, :M] @ Wx),  Bias = alpha_g*(b_g + W_g[:,:M]@bx + W_g[:,M:]@h0)
//   alpha = 0.5 (sigmoid gates i,f,o; sigma(z)=0.5*tanh(z/2)+0.5), 1.0 (tanh gate g)
// B image stored PRE-SWIZZLED in 16KB granules of 2 gates x 64 feats:
//   granule 0 = [i | g], granule 1 = [f | o]   (per stream, per 64-feat chunk)
// Main: CTA=(128 batch, stream), occ 3/SM, 3-slot cp.async granule ring.
// f-gate skipped per chunk when its c0 chunk is all zero (exact).
// ---------------------------------------------------------------------------

// [s][cch][granule] : granule = 128 rows x 64 fp16 K-cols (128B rows), SW128.
__device__ __align__(16) __half g_B[8 * 8 * 8192];
__device__ float g_Bias[8192];  // [(s*4+g)*256 + m], alpha-folded, g: 0=i,1=f,2=g,3=o

__device__ __forceinline__ uint32_t smem_u32(const void* p) {
    uint32_t a;
    asm("{ .reg .u64 t; cvta.to.shared.u64 t, %1; cvt.u32.u64 %0, t; }" : "=r"(a) : "l"(p));
    return a;
}
__device__ __forceinline__ float tanha(float x) {
    float y; asm("tanh.approx.f32 %0, %1;" : "=f"(y) : "f"(x)); return y;
}

#define SWZ(off) ((off) ^ (((off) >> 3) & 0x70))

#define LDSM4(r, addr)                                                          \
    asm volatile("ldmatrix.sync.aligned.m8n8.x4.shared.b16 {%0,%1,%2,%3}, [%4];" \
        : "=r"((r)[0]), "=r"((r)[1]), "=r"((r)[2]), "=r"((r)[3]) : "r"(addr))

#define MMA16816(d, a, b0, b1)                                                  \
    asm volatile("mma.sync.aligned.m16n8k16.row.col.f32.f16.f16.f32 "           \
        "{%0,%1,%2,%3}, {%4,%5,%6,%7}, {%8,%9}, {%0,%1,%2,%3};"                 \
        : "+f"((d)[0]), "+f"((d)[1]), "+f"((d)[2]), "+f"((d)[3])                \
        : "r"((a)[0]), "r"((a)[1]), "r"((a)[2]), "r"((a)[3]), "r"(b0), "r"(b1))

#define CPA_COMMIT() asm volatile("cp.async.commit_group;" ::: "memory")
#define CPW1() asm volatile("cp.async.wait_group 1;" ::: "memory")
#define CPW0() asm volatile("cp.async.wait_group 0;" ::: "memory")

// ---------------------------------------------------------------------------
// Precompute.  Blocks [0,512): weight composition (s,g,cch,mh,ih): 32m x 32i,
// K=256, written to gate-pair granule layout.  Blocks [512,2560): biases.
// ---------------------------------------------------------------------------
__global__ void __launch_bounds__(128) lnlstm_pre(
    const float* __restrict__ Wx,
    const float* __restrict__ Wi, const float* __restrict__ Wf,
    const float* __restrict__ Wg, const float* __restrict__ Wo,
    const float* __restrict__ bi, const float* __restrict__ bff,
    const float* __restrict__ bg, const float* __restrict__ bo,
    const float* __restrict__ bx, const float* __restrict__ h0)
{
    __shared__ float Wgs[32][68];
    __shared__ float Wxs[64][36];
    int bxid = blockIdx.x;
    int t = threadIdx.x;

    if (bxid < 512) {
        int s = bxid >> 6, g = (bxid >> 4) & 3, cch = (bxid >> 2) & 3;
        int mh = (bxid >> 1) & 1, ih = bxid & 1;
        const float* Wgate = (g == 0 ? Wi : g == 1 ? Wf : g == 2 ? Wg : Wo);
        int mg = t >> 4, ig = t & 15;

        float acc[8];
#pragma unroll
        for (int j = 0; j < 8; ++j) acc[j] = 0.f;

        for (int kt = 0; kt < 4; ++kt) {
            __syncthreads();
#pragma unroll
            for (int jj = 0; jj < 4; ++jj) {
                int idx = t + 128 * jj;
                int m = idx >> 4, kc = (idx & 15) * 4;
                *(float4*)&Wgs[m][kc] =
                    *(const float4*)&Wgate[(size_t)(s * 256 + cch * 64 + mh * 32 + m) * 512 + kt * 64 + kc];
            }
#pragma unroll
            for (int jj = 0; jj < 4; ++jj) {
                int idx = t + 128 * jj;
                int kk = idx >> 3, ic = (idx & 7) * 4;
                *(float4*)&Wxs[kk][ic] =
                    *(const float4*)&Wx[(size_t)(s * 256 + kt * 64 + kk) * 64 + ih * 32 + ic];
            }
            __syncthreads();
#pragma unroll 4
            for (int kk = 0; kk < 64; ++kk) {
                float w0 = Wgs[mg * 4 + 0][kk];
                float w1 = Wgs[mg * 4 + 1][kk];
                float w2 = Wgs[mg * 4 + 2][kk];
                float w3 = Wgs[mg * 4 + 3][kk];
                float2 wi = *(float2*)&Wxs[kk][ig * 2];
                acc[0] = fmaf(w0, wi.x, acc[0]);  acc[1] = fmaf(w0, wi.y, acc[1]);
                acc[2] = fmaf(w1, wi.x, acc[2]);  acc[3] = fmaf(w1, wi.y, acc[3]);
                acc[4] = fmaf(w2, wi.x, acc[4]);  acc[5] = fmaf(w2, wi.y, acc[5]);
                acc[6] = fmaf(w3, wi.x, acc[6]);  acc[7] = fmaf(w3, wi.y, acc[7]);
            }
        }

        float alpha = (g == 2) ? 1.0f : 0.5f;
        // granule layout: i->(gr0,row f), g->(gr0,64+f), f->(gr1,row f), o->(gr1,64+f)
        int gr = (g == 1 || g == 3) ? 1 : 0;
        int rb = (g >= 2) ? 64 : 0;
        size_t gbase = (size_t)s * 65536 + (size_t)(cch * 2 + gr) * 8192;
#pragma unroll
        for (int r = 0; r < 4; ++r) {
            int fl = mh * 32 + mg * 4 + r;
            int i = ih * 32 + ig * 2;
            __half2 h2 = __floats2half2_rn(acc[r * 2] * alpha, acc[r * 2 + 1] * alpha);
            uint32_t so = SWZ((uint32_t)((rb + fl) * 128 + i * 2));
            *(__half2*)&g_B[gbase + (so >> 1)] = h2;
        }
    } else {
        int wid = t >> 5, lane = t & 31;
        int id = (bxid - 512) * 4 + wid;
        int s = id >> 10, g = (id >> 8) & 3, m = id & 255;
        const float* W = (g == 0 ? Wi : g == 1 ? Wf : g == 2 ? Wg : Wo)
                         + (size_t)(s * 256 + m) * 512;
        const float* bb = (g == 0 ? bi : g == 1 ? bff : g == 2 ? bg : bo);
        float acc = 0.f;
#pragma unroll
        for (int it = 0; it < 4; ++it) {
            int k0 = it * 128 + lane * 4;
            float4 w = *(const float4*)&W[k0];
            float4 x = (it < 2) ? *(const float4*)&bx[s * 256 + k0]
                                : *(const float4*)&h0[s * 256 + k0 - 256];
            acc += w.x * x.x + w.y * x.y + w.z * x.z + w.w * x.w;
        }
#pragma unroll
        for (int d = 16; d > 0; d >>= 1)
            acc += __shfl_xor_sync(0xFFFFFFFFu, acc, d);
        if (lane == 0) {
            float alpha = (g == 2) ? 1.0f : 0.5f;
            g_Bias[id] = alpha * (bb[s * 256 + m] + acc);
        }
    }
}

// ---------------------------------------------------------------------------
// Main kernel.  SMEM: bias 4KB | c0 1KB | flags | A 16KB | B ring 3x16KB.
// 8 warps (4m x 2f over 128 rows x 32 feats per pass); 2 passes per chunk.
// ---------------------------------------------------------------------------
static constexpr unsigned SMEM_BYTES = 6144 + 16384 + 3 * 16384 + 1024;

__device__ __forceinline__ void prefetch_G(uint32_t dst, const __half* src, int tid) {
#pragma unroll
    for (int j = 0; j < 4; ++j) {
        uint32_t d = dst + tid * 16 + j * 4096;
        const char* sp = (const char*)src + tid * 16 + j * 4096;
        asm volatile("cp.async.cg.shared.global [%0], [%1], 16;" :: "r"(d), "l"(sp));
    }
    CPA_COMMIT();
}

__device__ __forceinline__ void gate_gemm(
    float acc[2][2][4], const uint32_t afr[4][2][4],
    uint32_t gbase, int row0, int rowB, int colB,
    const float* bias_p, int lane)
{
    float2 b0 = *(const float2*)(bias_p + (lane & 3) * 2);
    float2 b1 = *(const float2*)(bias_p + 8 + (lane & 3) * 2);
#pragma unroll
    for (int mt = 0; mt < 2; ++mt) {
        acc[mt][0][0] = b0.x; acc[mt][0][1] = b0.y; acc[mt][0][2] = b0.x; acc[mt][0][3] = b0.y;
        acc[mt][1][0] = b1.x; acc[mt][1][1] = b1.y; acc[mt][1][2] = b1.x; acc[mt][1][3] = b1.y;
    }
#pragma unroll
    for (int ks = 0; ks < 4; ++ks) {
        uint32_t bfr[4];
        LDSM4(bfr, gbase + SWZ((uint32_t)((row0 + rowB) * 128 + ks * 32 + colB)));
        MMA16816(acc[0][0], afr[ks][0], bfr[0], bfr[1]);
        MMA16816(acc[0][1], afr[ks][0], bfr[2], bfr[3]);
        MMA16816(acc[1][0], afr[ks][1], bfr[0], bfr[1]);
        MMA16816(acc[1][1], afr[ks][1], bfr[2], bfr[3]);
    }
}

__global__ void __launch_bounds__(256, 3)
lnlstm_main(const float* __restrict__ mod, const float* __restrict__ c0g, float* __restrict__ out)
{
    extern __shared__ char dsm[];
    uint32_t sb = smem_u32(dsm);
    uint32_t ab = (sb + 1023u) & ~1023u;
    char* base = dsm + (ab - sb);

    float* bias_s = (float*)base;            // 4KB [g*256 + cch*64 + f]
    float* c0_s = (float*)(base + 4096);     // 1KB
    int* c0nz = (int*)(base + 5120);
    char* Ap = base + 6144;                  // 16KB
    const uint32_t Aa = ab + 6144;
    const uint32_t Ba = Aa + 16384;          // ring of 3 x 16KB

    int tid = threadIdx.x;
    int lane = tid & 31, w = tid >> 5;
    int bx = blockIdx.x;
    int s = bx >> 7, b = bx & 127;
    int n0 = b * 128;
    int mbase = (w >> 1) * 32;
    int fhalf = (w & 1) * 16;

    const __half* img = g_B + (size_t)s * 65536;
    prefetch_G(Ba, img, tid);                 // G0 -> slot 0
    prefetch_G(Ba + 16384, img + 8192, tid);  // G1 -> slot 1

    if (tid < 4) c0nz[tid] = 0;
#pragma unroll
    for (int j = 0; j < 4; ++j) bias_s[tid + 256 * j] = g_Bias[s * 1024 + tid + 256 * j];
    {
        float cv = c0g[s * 256 + tid];
        c0_s[tid] = cv;
        if (cv != 0.0f) atomicOr(&c0nz[tid >> 6], 1);
    }

    // --- A tile: fp32 mod -> fp16, swizzled (128 rows x 64 cols) ---
    {
        const float* mp = mod + (size_t)n0 * 512 + s * 64;
#pragma unroll
        for (int j = 0; j < 8; ++j) {
            int idx = tid + 256 * j;
            int r = idx >> 4, q = idx & 15;
            float4 v = *(const float4*)(mp + (size_t)r * 512 + q * 4);
            __half2 h01 = __floats2half2_rn(v.x, v.y);
            __half2 h23 = __floats2half2_rn(v.z, v.w);
            uint2 pk;
            pk.x = *(uint32_t*)&h01;
            pk.y = *(uint32_t*)&h23;
            uint32_t so = SWZ((uint32_t)(r * 128 + q * 8));
            *(uint2*)(Ap + so) = pk;
        }
    }
    __syncthreads();

    const int rowA = lane & 15;
    const int colA = (lane >> 4) * 16;
    const int rowB = (lane & 7) + ((lane >> 4) << 3);
    const int colB = ((lane >> 3) & 1) * 16;

    uint32_t afr[4][2][4];
#pragma unroll
    for (int ks = 0; ks < 4; ++ks)
#pragma unroll
        for (int mt = 0; mt < 2; ++mt) {
            uint32_t addr = Aa + SWZ((uint32_t)((mbase + mt * 16 + rowA) * 128 + ks * 32 + colA));
            LDSM4(afr[ks][mt], addr);
        }

#pragma unroll 1
    for (int cch = 0; cch < 4; ++cch) {
        const uint32_t gA = Ba + ((2 * cch) % 3) * 16384;
        const uint32_t gB = Ba + ((2 * cch + 1) % 3) * 16384;
        CPW1();                                   // granule 2c landed
        __syncthreads();                          // visibility + prior chunk done
        if (cch < 3)                              // G(2c+2) -> slot of G(2c-1)
            prefetch_G(Ba + ((2 * cch + 2) % 3) * 16384,
                       img + (size_t)(2 * cch + 2) * 8192, tid);
        const int fgate_on = c0nz[cch];

#pragma unroll
        for (int fg = 0; fg < 2; ++fg) {
            const int fl = fg * 32 + fhalf;       // chunk-local feat base (16 feats)
            float P[2][2][4];
            float acc[2][2][4];

            // i-gate (granule A, rows 0..63)
            gate_gemm(acc, afr, gA, fl, rowB, colB, &bias_s[0 * 256 + cch * 64 + fl], lane);
#pragma unroll
            for (int mt = 0; mt < 2; ++mt)
#pragma unroll
                for (int nt = 0; nt < 2; ++nt)
#pragma unroll
                    for (int q = 0; q < 4; ++q)
                        P[mt][nt][q] = fmaf(tanha(acc[mt][nt][q]), 0.5f, 0.5f);

            // g-gate (granule A, rows 64..127)
            gate_gemm(acc, afr, gA, 64 + fl, rowB, colB, &bias_s[2 * 256 + cch * 64 + fl], lane);
#pragma unroll
            for (int mt = 0; mt < 2; ++mt)
#pragma unroll
                for (int nt = 0; nt < 2; ++nt)
#pragma unroll
                    for (int q = 0; q < 4; ++q)
                        P[mt][nt][q] *= tanha(acc[mt][nt][q]);

            if (fg == 0) {                        // granule B must be resident
                if (cch == 3) CPW0(); else CPW1();
                __syncthreads();
            } else {                              // granule A fully consumed
                __syncthreads();
                if (cch < 3)                      // G(2c+3) -> slot of G(2c)
                    prefetch_G(Ba + ((2 * cch + 3) % 3) * 16384,
                               img + (size_t)(2 * cch + 3) * 8192, tid);
            }

            // f-gate (granule B, rows 0..63) -- skipped when c0 chunk == 0
            if (fgate_on) {
                gate_gemm(acc, afr, gB, fl, rowB, colB, &bias_s[1 * 256 + cch * 64 + fl], lane);
#pragma unroll
                for (int mt = 0; mt < 2; ++mt)
#pragma unroll
                    for (int nt = 0; nt < 2; ++nt) {
                        float2 c02 = *(float2*)&c0_s[cch * 64 + fl + nt * 8 + (lane & 3) * 2];
#pragma unroll
                        for (int q = 0; q < 4; ++q) {
                            float c0v = (q & 1) ? c02.y : c02.x;
                            P[mt][nt][q] = fmaf(fmaf(tanha(acc[mt][nt][q]), 0.5f, 0.5f), c0v, P[mt][nt][q]);
                        }
                    }
            }

            // o-gate (granule B, rows 64..127) + final combine + store
            gate_gemm(acc, afr, gB, 64 + fl, rowB, colB, &bias_s[3 * 256 + cch * 64 + fl], lane);
            float* orow0 = out + (size_t)(n0 + mbase + (lane >> 2)) * 2048
                           + s * 256 + cch * 64 + fl + (lane & 3) * 2;
#pragma unroll
            for (int mt = 0; mt < 2; ++mt)
#pragma unroll
                for (int nt = 0; nt < 2; ++nt) {
                    float h0v = fmaf(tanha(acc[mt][nt][0]), 0.5f, 0.5f) * tanha(P[mt][nt][0]);
                    float h1v = fmaf(tanha(acc[mt][nt][1]), 0.5f, 0.5f) * tanha(P[mt][nt][1]);
                    float h2v = fmaf(tanha(acc[mt][nt][2]), 0.5f, 0.5f) * tanha(P[mt][nt][2]);
                    float h3v = fmaf(tanha(acc[mt][nt][3]), 0.5f, 0.5f) * tanha(P[mt][nt][3]);
                    float* p0 = orow0 + (size_t)(mt * 16) * 2048 + nt * 8;
                    *(float2*)p0 = make_float2(h0v, h1v);
                    *(float2*)(p0 + (size_t)8 * 2048) = make_float2(h2v, h3v);
                }
        }
    }
}

// ---------------------------------------------------------------------------
extern "C" void kernel_launch(void* const* d_in, const int* in_sizes, int n_in,
                              void* d_out, int out_size)
{
    const float* mod = (const float*)d_in[0];
    const float* h0  = (const float*)d_in[1];
    const float* c0  = (const float*)d_in[2];
    const float* Wx  = (const float*)d_in[3];
    const float* bxp = (const float*)d_in[4];
    const float* Wi  = (const float*)d_in[5];
    const float* bi  = (const float*)d_in[6];
    const float* Wf  = (const float*)d_in[7];
    const float* bfp = (const float*)d_in[8];
    const float* Wg  = (const float*)d_in[9];
    const float* bg  = (const float*)d_in[10];
    const float* Wo  = (const float*)d_in[11];
    const float* bo  = (const float*)d_in[12];
    float* out = (float*)d_out;

    cudaFuncSetAttribute(lnlstm_main, cudaFuncAttributeMaxDynamicSharedMemorySize, SMEM_BYTES);

    lnlstm_pre<<<2560, 128>>>(Wx, Wi, Wf, Wg, Wo, bi, bfp, bg, bo, bxp, h0);
    lnlstm_main<<<1024, 256, SMEM_BYTES>>>(mod, c0, out);
}

// round 11
// speedup vs baseline: 1.1124x; 1.1124x over previous
#include <cuda_runtime.h>
#include <cuda_fp16.h>
#include <cstdint>

// ---------------------------------------------------------------------------
// S=8 streams, I=64 mod dims, M=256 features, N=16384 batch.
// Collapsed math:  z_g[n,s,m] = sum_i C_g[s,m,i]*mod[n,s,i] + Bias[s,g,m]
//   C_g  = alpha_g * (W_g[:, :M] @ Wx),  Bias = alpha_g*(b_g + W_g[:,:M]@bx + W_g[:,M:]@h0)
//   alpha = 0.5 (sigmoid gates i,f,o; sigma(z)=0.5*tanh(z/2)+0.5), 1.0 (tanh gate g)
// Composition runs on tensor cores with a 3-term fp16 hi/lo split (error ~2^-21,
// i.e. identical to an fp32 compose after the final fp16 rounding of C).
// Main kernel: R8 structure (2-deep 32KB cp.async double buffer, 8 warps,
// 64-feat warp N-tile, bias preloaded in accumulators, f-gate skip).
// ---------------------------------------------------------------------------

// Composed weights, fp16, PRE-SWIZZLED (exact SW128 SMEM image).
// [s][chunk] slab: 256 rows (n = gate*64 + f) x 64 fp16 K-cols (128B rows).
__device__ __align__(16) __half g_B[8 * 4 * 16384];
__device__ float g_Bias[8192];  // [(s*4+g)*256 + m], alpha-folded, g: 0=i,1=f,2=g,3=o

__device__ __forceinline__ uint32_t smem_u32(const void* p) {
    uint32_t a;
    asm("{ .reg .u64 t; cvta.to.shared.u64 t, %1; cvt.u32.u64 %0, t; }" : "=r"(a) : "l"(p));
    return a;
}
__device__ __forceinline__ float tanha(float x) {
    float y; asm("tanh.approx.f32 %0, %1;" : "=f"(y) : "f"(x)); return y;
}

#define SWZ(off) ((off) ^ (((off) >> 3) & 0x70))

#define LDSM4(r, addr)                                                          \
    asm volatile("ldmatrix.sync.aligned.m8n8.x4.shared.b16 {%0,%1,%2,%3}, [%4];" \
        : "=r"((r)[0]), "=r"((r)[1]), "=r"((r)[2]), "=r"((r)[3]) : "r"(addr))

#define MMA16816(d, a, b0, b1)                                                  \
    asm volatile("mma.sync.aligned.m16n8k16.row.col.f32.f16.f16.f32 "           \
        "{%0,%1,%2,%3}, {%4,%5,%6,%7}, {%8,%9}, {%0,%1,%2,%3};"                 \
        : "+f"((d)[0]), "+f"((d)[1]), "+f"((d)[2]), "+f"((d)[3])                \
        : "r"((a)[0]), "r"((a)[1]), "r"((a)[2]), "r"((a)[3]), "r"(b0), "r"(b1))

#define CPA_COMMIT() asm volatile("cp.async.commit_group;" ::: "memory")

// ---------------------------------------------------------------------------
// Precompute.  Blocks [0,128): tensor-core composition, one per (s,g,chunk):
// C tile 64m x 64i, K=256 staged in 4 k64 slices, 3-term fp16 hi/lo split.
// Blocks [128,1152): biases, 8 warps each (one warp per output).
// ---------------------------------------------------------------------------
__global__ void __launch_bounds__(256) lnlstm_pre(
    const float* __restrict__ Wx,
    const float* __restrict__ Wi, const float* __restrict__ Wf,
    const float* __restrict__ Wg, const float* __restrict__ Wo,
    const float* __restrict__ bi, const float* __restrict__ bff,
    const float* __restrict__ bg, const float* __restrict__ bo,
    const float* __restrict__ bx, const float* __restrict__ h0)
{
    // 4 x 8KB swizzled fp16 tiles (64 rows x 64 cols, 128B rows)
    __shared__ __align__(16) __half Ahi[4096], Alo[4096], BhiS[4096], BloS[4096];
    int bxid = blockIdx.x;
    int t = threadIdx.x;
    int lane = t & 31, w = t >> 5;

    if (bxid < 128) {
        int s = bxid >> 4, g = (bxid >> 2) & 3, mh = bxid & 3;   // mh == feature chunk
        const float* Wgate = (g == 0 ? Wi : g == 1 ? Wf : g == 2 ? Wg : Wo);
        const uint32_t AhiA = smem_u32(Ahi), AloA = smem_u32(Alo);
        const uint32_t BhiA = smem_u32(BhiS), BloA = smem_u32(BloS);

        int mw = w >> 1, iw = w & 1;                 // warp tile: 16m x 32i
        const int rowA = lane & 15, colA = (lane >> 4) * 16;
        const int rowB = (lane & 7) + ((lane >> 4) << 3), colB = ((lane >> 3) & 1) * 16;

        float acc[4][4];
#pragma unroll
        for (int nt = 0; nt < 4; ++nt)
#pragma unroll
            for (int q = 0; q < 4; ++q) acc[nt][q] = 0.f;

        for (int kt = 0; kt < 4; ++kt) {
            __syncthreads();
            // A slice: Wg[mh*64+row][kt*64 + k], 64x64 fp32 -> hi/lo fp16, swizzled
#pragma unroll
            for (int j = 0; j < 4; ++j) {
                int idx = t + 256 * j;
                int row = idx >> 4, c4 = (idx & 15) * 4;
                float4 v = *(const float4*)&Wgate[(size_t)(s * 256 + mh * 64 + row) * 512 + kt * 64 + c4];
                __half hx = __float2half_rn(v.x), hy = __float2half_rn(v.y);
                __half hz = __float2half_rn(v.z), hw = __float2half_rn(v.w);
                __half2 hiA = __halves2half2(hx, hy), hiB = __halves2half2(hz, hw);
                __half2 loA = __floats2half2_rn(v.x - __half2float(hx), v.y - __half2float(hy));
                __half2 loB = __floats2half2_rn(v.z - __half2float(hz), v.w - __half2float(hw));
                uint32_t o0 = SWZ((uint32_t)(row * 128 + c4 * 2));
                uint32_t o1 = SWZ((uint32_t)(row * 128 + c4 * 2 + 4));
                *(__half2*)((char*)Ahi + o0) = hiA;  *(__half2*)((char*)Ahi + o1) = hiB;
                *(__half2*)((char*)Alo + o0) = loA;  *(__half2*)((char*)Alo + o1) = loB;
            }
            // B slice: Wx[s][kt*64+krow][i], transposed to [i][k], hi/lo, swizzled
#pragma unroll
            for (int j = 0; j < 4; ++j) {
                int idx = t + 256 * j;
                int krow = idx >> 4, i4 = (idx & 15) * 4;
                float4 v = *(const float4*)&Wx[(size_t)(s * 256 + kt * 64 + krow) * 64 + i4];
                float vv[4] = {v.x, v.y, v.z, v.w};
#pragma unroll
                for (int c = 0; c < 4; ++c) {
                    __half hi = __float2half_rn(vv[c]);
                    __half lo = __float2half_rn(vv[c] - __half2float(hi));
                    uint32_t so = SWZ((uint32_t)((i4 + c) * 128 + krow * 2));
                    *(__half*)((char*)BhiS + so) = hi;
                    *(__half*)((char*)BloS + so) = lo;
                }
            }
            __syncthreads();
#pragma unroll
            for (int ks = 0; ks < 4; ++ks) {
                uint32_t ah[4], al[4];
                uint32_t aoff = SWZ((uint32_t)((mw * 16 + rowA) * 128 + ks * 32 + colA));
                LDSM4(ah, AhiA + aoff);
                LDSM4(al, AloA + aoff);
#pragma unroll
                for (int ntp = 0; ntp < 2; ++ntp) {
                    uint32_t bh[4], bl[4];
                    uint32_t boff = SWZ((uint32_t)((iw * 32 + ntp * 16 + rowB) * 128 + ks * 32 + colB));
                    LDSM4(bh, BhiA + boff);
                    LDSM4(bl, BloA + boff);
                    MMA16816(acc[2 * ntp + 0], ah, bh[0], bh[1]);
                    MMA16816(acc[2 * ntp + 1], ah, bh[2], bh[3]);
                    MMA16816(acc[2 * ntp + 0], al, bh[0], bh[1]);
                    MMA16816(acc[2 * ntp + 1], al, bh[2], bh[3]);
                    MMA16816(acc[2 * ntp + 0], ah, bl[0], bl[1]);
                    MMA16816(acc[2 * ntp + 1], ah, bl[2], bl[3]);
                }
            }
        }

        float alpha = (g == 2) ? 1.0f : 0.5f;
        size_t ibase = (size_t)(s * 4 + mh) * 16384;
        int fl = mw * 16 + (lane >> 2);              // chunk-local feature (row in C tile)
#pragma unroll
        for (int nt = 0; nt < 4; ++nt) {
            int i = iw * 32 + nt * 8 + (lane & 3) * 2;
            int n0r = g * 64 + fl;
            __half2 h01 = __floats2half2_rn(acc[nt][0] * alpha, acc[nt][1] * alpha);
            __half2 h23 = __floats2half2_rn(acc[nt][2] * alpha, acc[nt][3] * alpha);
            uint32_t so0 = SWZ((uint32_t)(n0r * 128 + i * 2));
            uint32_t so1 = SWZ((uint32_t)((n0r + 8) * 128 + i * 2));
            *(__half2*)&g_B[ibase + (so0 >> 1)] = h01;
            *(__half2*)&g_B[ibase + (so1 >> 1)] = h23;
        }
    } else {
        // ---- bias: one warp per output (coalesced float4 dot over K=512) ----
        int id = (bxid - 128) * 8 + w;  // < 8192
        int s = id >> 10, g = (id >> 8) & 3, m = id & 255;
        const float* W = (g == 0 ? Wi : g == 1 ? Wf : g == 2 ? Wg : Wo)
                         + (size_t)(s * 256 + m) * 512;
        const float* bb = (g == 0 ? bi : g == 1 ? bff : g == 2 ? bg : bo);
        float acc = 0.f;
#pragma unroll
        for (int it = 0; it < 4; ++it) {
            int k0 = it * 128 + lane * 4;
            float4 wv = *(const float4*)&W[k0];
            float4 x = (it < 2) ? *(const float4*)&bx[s * 256 + k0]
                                : *(const float4*)&h0[s * 256 + k0 - 256];
            acc += wv.x * x.x + wv.y * x.y + wv.z * x.z + wv.w * x.w;
        }
#pragma unroll
        for (int d = 16; d > 0; d >>= 1)
            acc += __shfl_xor_sync(0xFFFFFFFFu, acc, d);
        if (lane == 0) {
            float alpha = (g == 2) ? 1.0f : 0.5f;
            g_Bias[id] = alpha * (bb[s * 256 + m] + acc);
        }
    }
}

// ---------------------------------------------------------------------------
// Main kernel (R8 structure): CTA = (128-batch tile, stream). 256 thr, 8 warps
// (4m x 2f, 64-feat warp N-tile). A tile + fragments ONCE; 4 feature chunks
// with double-buffered 32KB cp.async; bias preloaded in acc; f-gate skip.
// SMEM (1024-aligned): bias 4KB | c0 1KB | flags | A 16KB | B0 32KB | B1 32KB
// ---------------------------------------------------------------------------
static constexpr unsigned SMEM_BYTES = 90112 + 1024;

__device__ __forceinline__ void prefetch_B(uint32_t dstA, const __half* slab, int tid) {
#pragma unroll
    for (int j = 0; j < 8; ++j) {
        uint32_t d = dstA + tid * 16 + j * 4096;
        const char* sp = (const char*)slab + tid * 16 + j * 4096;
        asm volatile("cp.async.cg.shared.global [%0], [%1], 16;" :: "r"(d), "l"(sp));
    }
    CPA_COMMIT();
}

__global__ void __launch_bounds__(256, 2)
lnlstm_main(const float* __restrict__ mod, const float* __restrict__ c0g, float* __restrict__ out)
{
    extern __shared__ char dsm[];
    uint32_t sb = smem_u32(dsm);
    uint32_t ab = (sb + 1023u) & ~1023u;
    char* base = dsm + (ab - sb);

    float* bias_s = (float*)base;            // 4KB: [g*256 + cch*64 + f]
    float* c0_s = (float*)(base + 4096);     // 1KB
    int* c0nz = (int*)(base + 5120);         // 4 flags
    char* Ap = base + 8192;                  // 16KB: [128 rows][128B]
    const uint32_t Aa = ab + 8192;
    const uint32_t Ba0 = Aa + 16384, Ba1 = Ba0 + 32768;

    int tid = threadIdx.x;
    int lane = tid & 31, w = tid >> 5;
    int bx = blockIdx.x;
    int s = bx >> 7, b = bx & 127;
    int n0 = b * 128;
    int mbase = (w >> 1) * 32;
    int fbase = (w & 1) * 32;

    const __half* slab = g_B + (size_t)s * 4 * 16384;
    prefetch_B(Ba0, slab, tid);
    prefetch_B(Ba1, slab + 16384, tid);

    if (tid < 4) c0nz[tid] = 0;
#pragma unroll
    for (int j = 0; j < 4; ++j) bias_s[tid + 256 * j] = g_Bias[s * 1024 + tid + 256 * j];
    {
        float cv = c0g[s * 256 + tid];
        c0_s[tid] = cv;
        if (cv != 0.0f) atomicOr(&c0nz[tid >> 6], 1);
    }

    // --- A tile: fp32 mod -> fp16, swizzled store (128 rows x 64 cols) ---
    {
        const float* mp = mod + (size_t)n0 * 512 + s * 64;
#pragma unroll
        for (int j = 0; j < 8; ++j) {
            int idx = tid + 256 * j;
            int r = idx >> 4, q = idx & 15;
            float4 v = *(const float4*)(mp + (size_t)r * 512 + q * 4);
            __half2 h01 = __floats2half2_rn(v.x, v.y);
            __half2 h23 = __floats2half2_rn(v.z, v.w);
            uint2 pk;
            pk.x = *(uint32_t*)&h01;
            pk.y = *(uint32_t*)&h23;
            uint32_t so = SWZ((uint32_t)(r * 128 + q * 8));
            *(uint2*)(Ap + so) = pk;
        }
    }
    __syncthreads();

    const int rowA = lane & 15;
    const int colA = (lane >> 4) * 16;
    const int rowB = (lane & 7) + ((lane >> 4) << 3);
    const int colB = ((lane >> 3) & 1) * 16;

    // --- preload ALL A fragments (reused across chunks AND gates) ---
    uint32_t afr[4][2][4];
#pragma unroll
    for (int ks = 0; ks < 4; ++ks)
#pragma unroll
        for (int mt = 0; mt < 2; ++mt) {
            uint32_t addr = Aa + SWZ((uint32_t)((mbase + mt * 16 + rowA) * 128 + ks * 32 + colA));
            LDSM4(afr[ks][mt], addr);
        }

    for (int cch = 0; cch < 4; ++cch) {
        if (cch == 3) asm volatile("cp.async.wait_group 0;" ::: "memory");
        else         asm volatile("cp.async.wait_group 1;" ::: "memory");
        __syncthreads();
        const uint32_t Bcur = (cch & 1) ? Ba1 : Ba0;
        const int fgate_on = c0nz[cch];

        float P[2][4][4];
        float* orow0 = out + (size_t)(n0 + mbase + (lane >> 2)) * 2048
                       + s * 256 + cch * 64 + fbase + (lane & 3) * 2;

#pragma unroll
        for (int step = 0; step < 4; ++step) {
            const int gsel = (step == 0) ? 0 : (step == 1) ? 2 : (step == 2) ? 1 : 3;  // i,g,f,o
            if (step == 2 && !fgate_on) continue;      // f*c0 == 0 exactly

            float2 bias2[4];
#pragma unroll
            for (int nt = 0; nt < 4; ++nt)
                bias2[nt] = *(float2*)&bias_s[gsel * 256 + cch * 64 + fbase + nt * 8 + (lane & 3) * 2];

            float acc[2][4][4];
#pragma unroll
            for (int mt = 0; mt < 2; ++mt)
#pragma unroll
                for (int nt = 0; nt < 4; ++nt) {
                    acc[mt][nt][0] = bias2[nt].x; acc[mt][nt][1] = bias2[nt].y;
                    acc[mt][nt][2] = bias2[nt].x; acc[mt][nt][3] = bias2[nt].y;
                }

#pragma unroll
            for (int ks = 0; ks < 4; ++ks) {
#pragma unroll
                for (int ntp = 0; ntp < 2; ++ntp) {
                    uint32_t bfr[4];
                    uint32_t addr = Bcur + SWZ((uint32_t)((gsel * 64 + fbase + ntp * 16 + rowB) * 128 + ks * 32 + colB));
                    LDSM4(bfr, addr);
                    MMA16816(acc[0][2 * ntp + 0], afr[ks][0], bfr[0], bfr[1]);
                    MMA16816(acc[0][2 * ntp + 1], afr[ks][0], bfr[2], bfr[3]);
                    MMA16816(acc[1][2 * ntp + 0], afr[ks][1], bfr[0], bfr[1]);
                    MMA16816(acc[1][2 * ntp + 1], afr[ks][1], bfr[2], bfr[3]);
                }
            }

#pragma unroll
            for (int mt = 0; mt < 2; ++mt) {
#pragma unroll
                for (int nt = 0; nt < 4; ++nt) {
#pragma unroll
                    for (int q = 0; q < 4; ++q) {
                        float tz = tanha(acc[mt][nt][q]);
                        if (step == 0) {
                            P[mt][nt][q] = fmaf(tz, 0.5f, 0.5f);
                        } else if (step == 1) {
                            P[mt][nt][q] *= tz;
                        } else if (step == 2) {
                            float2 c02 = *(float2*)&c0_s[cch * 64 + fbase + nt * 8 + (lane & 3) * 2];
                            float c0v = (q & 1) ? c02.y : c02.x;
                            P[mt][nt][q] = fmaf(fmaf(tz, 0.5f, 0.5f), c0v, P[mt][nt][q]);
                        } else {
                            float so = fmaf(tz, 0.5f, 0.5f);
                            P[mt][nt][q] = so * tanha(P[mt][nt][q]);
                        }
                    }
                }
            }
        }

#pragma unroll
        for (int mt = 0; mt < 2; ++mt) {
#pragma unroll
            for (int nt = 0; nt < 4; ++nt) {
                float* p0 = orow0 + (size_t)(mt * 16) * 2048 + nt * 8;
                *(float2*)p0 = make_float2(P[mt][nt][0], P[mt][nt][1]);
                *(float2*)(p0 + (size_t)8 * 2048) = make_float2(P[mt][nt][2], P[mt][nt][3]);
            }
        }

        __syncthreads();
        if (cch < 2) prefetch_B(Bcur, slab + (cch + 2) * 16384, tid);
    }
}

// ---------------------------------------------------------------------------
extern "C" void kernel_launch(void* const* d_in, const int* in_sizes, int n_in,
                              void* d_out, int out_size)
{
    const float* mod = (const float*)d_in[0];
    const float* h0  = (const float*)d_in[1];
    const float* c0  = (const float*)d_in[2];
    const float* Wx  = (const float*)d_in[3];
    const float* bxp = (const float*)d_in[4];
    const float* Wi  = (const float*)d_in[5];
    const float* bi  = (const float*)d_in[6];
    const float* Wf  = (const float*)d_in[7];
    const float* bfp = (const float*)d_in[8];
    const float* Wg  = (const float*)d_in[9];
    const float* bg  = (const float*)d_in[10];
    const float* Wo  = (const float*)d_in[11];
    const float* bo  = (const float*)d_in[12];
    float* out = (float*)d_out;

    cudaFuncSetAttribute(lnlstm_main, cudaFuncAttributeMaxDynamicSharedMemorySize, SMEM_BYTES);

    lnlstm_pre<<<1152, 256>>>(Wx, Wi, Wf, Wg, Wo, bi, bfp, bg, bo, bxp, h0);
    lnlstm_main<<<1024, 256, SMEM_BYTES>>>(mod, c0, out);
}

// round 12
// speedup vs baseline: 1.1319x; 1.0175x over previous
#include <cuda_runtime.h>
#include <cuda_fp16.h>
#include <cstdint>

// ---------------------------------------------------------------------------
// S=8 streams, I=64 mod dims, M=256 features, N=16384 batch.
// Collapsed math:  z_g[n,s,m] = sum_i C_g[s,m,i]*mod[n,s,i] + Bias[s,g,m]
//   C_g  = alpha_g * (W_g[:, :M] @ Wx),  Bias = alpha_g*(b_g + W_g[:,:M]@bx + W_g[:,M:]@h0)
//   alpha = 0.5 (sigmoid gates i,f,o; sigma(z)=0.5*tanh(z/2)+0.5), 1.0 (tanh gate g)
// Composition on tensor cores with 3-term fp16 hi/lo split (error ~2^-21).
// Main kernel: 8 warps (4m x 2f), A fragments register-resident, 4 feature
// chunks with double-buffered cp.async at prefetch distance 1 and a SINGLE
// __syncthreads per chunk (epilogue+stores overlap next chunk's MMA).
// f-gate skipped per chunk when its c0 chunk is all zero (exact).
// ---------------------------------------------------------------------------

// Composed weights, fp16, PRE-SWIZZLED (exact SW128 SMEM image).
// [s][chunk] slab: 256 rows (n = gate*64 + f) x 64 fp16 K-cols (128B rows).
__device__ __align__(16) __half g_B[8 * 4 * 16384];
__device__ float g_Bias[8192];  // [(s*4+g)*256 + m], alpha-folded, g: 0=i,1=f,2=g,3=o

__device__ __forceinline__ uint32_t smem_u32(const void* p) {
    uint32_t a;
    asm("{ .reg .u64 t; cvta.to.shared.u64 t, %1; cvt.u32.u64 %0, t; }" : "=r"(a) : "l"(p));
    return a;
}
__device__ __forceinline__ float tanha(float x) {
    float y; asm("tanh.approx.f32 %0, %1;" : "=f"(y) : "f"(x)); return y;
}

#define SWZ(off) ((off) ^ (((off) >> 3) & 0x70))

#define LDSM4(r, addr)                                                          \
    asm volatile("ldmatrix.sync.aligned.m8n8.x4.shared.b16 {%0,%1,%2,%3}, [%4];" \
        : "=r"((r)[0]), "=r"((r)[1]), "=r"((r)[2]), "=r"((r)[3]) : "r"(addr))

#define MMA16816(d, a, b0, b1)                                                  \
    asm volatile("mma.sync.aligned.m16n8k16.row.col.f32.f16.f16.f32 "           \
        "{%0,%1,%2,%3}, {%4,%5,%6,%7}, {%8,%9}, {%0,%1,%2,%3};"                 \
        : "+f"((d)[0]), "+f"((d)[1]), "+f"((d)[2]), "+f"((d)[3])                \
        : "r"((a)[0]), "r"((a)[1]), "r"((a)[2]), "r"((a)[3]), "r"(b0), "r"(b1))

#define CPA_COMMIT() asm volatile("cp.async.commit_group;" ::: "memory")

// ---------------------------------------------------------------------------
// Precompute.  Blocks [0,128): tensor-core composition, one per (s,g,chunk):
// C tile 64m x 64i, K=256 staged in 4 k64 slices, 3-term fp16 hi/lo split.
// Blocks [128,1152): biases, 8 warps each (one warp per output).
// ---------------------------------------------------------------------------
__global__ void __launch_bounds__(256) lnlstm_pre(
    const float* __restrict__ Wx,
    const float* __restrict__ Wi, const float* __restrict__ Wf,
    const float* __restrict__ Wg, const float* __restrict__ Wo,
    const float* __restrict__ bi, const float* __restrict__ bff,
    const float* __restrict__ bg, const float* __restrict__ bo,
    const float* __restrict__ bx, const float* __restrict__ h0)
{
    __shared__ __align__(16) __half Ahi[4096], Alo[4096], BhiS[4096], BloS[4096];
    int bxid = blockIdx.x;
    int t = threadIdx.x;
    int lane = t & 31, w = t >> 5;

    if (bxid < 128) {
        int s = bxid >> 4, g = (bxid >> 2) & 3, mh = bxid & 3;   // mh == feature chunk
        const float* Wgate = (g == 0 ? Wi : g == 1 ? Wf : g == 2 ? Wg : Wo);
        const uint32_t AhiA = smem_u32(Ahi), AloA = smem_u32(Alo);
        const uint32_t BhiA = smem_u32(BhiS), BloA = smem_u32(BloS);

        int mw = w >> 1, iw = w & 1;                 // warp tile: 16m x 32i
        const int rowA = lane & 15, colA = (lane >> 4) * 16;
        const int rowB = (lane & 7) + ((lane >> 4) << 3), colB = ((lane >> 3) & 1) * 16;

        float acc[4][4];
#pragma unroll
        for (int nt = 0; nt < 4; ++nt)
#pragma unroll
            for (int q = 0; q < 4; ++q) acc[nt][q] = 0.f;

        for (int kt = 0; kt < 4; ++kt) {
            __syncthreads();
#pragma unroll
            for (int j = 0; j < 4; ++j) {
                int idx = t + 256 * j;
                int row = idx >> 4, c4 = (idx & 15) * 4;
                float4 v = *(const float4*)&Wgate[(size_t)(s * 256 + mh * 64 + row) * 512 + kt * 64 + c4];
                __half hx = __float2half_rn(v.x), hy = __float2half_rn(v.y);
                __half hz = __float2half_rn(v.z), hw = __float2half_rn(v.w);
                __half2 hiA = __halves2half2(hx, hy), hiB = __halves2half2(hz, hw);
                __half2 loA = __floats2half2_rn(v.x - __half2float(hx), v.y - __half2float(hy));
                __half2 loB = __floats2half2_rn(v.z - __half2float(hz), v.w - __half2float(hw));
                uint32_t o0 = SWZ((uint32_t)(row * 128 + c4 * 2));
                uint32_t o1 = SWZ((uint32_t)(row * 128 + c4 * 2 + 4));
                *(__half2*)((char*)Ahi + o0) = hiA;  *(__half2*)((char*)Ahi + o1) = hiB;
                *(__half2*)((char*)Alo + o0) = loA;  *(__half2*)((char*)Alo + o1) = loB;
            }
#pragma unroll
            for (int j = 0; j < 4; ++j) {
                int idx = t + 256 * j;
                int krow = idx >> 4, i4 = (idx & 15) * 4;
                float4 v = *(const float4*)&Wx[(size_t)(s * 256 + kt * 64 + krow) * 64 + i4];
                float vv[4] = {v.x, v.y, v.z, v.w};
#pragma unroll
                for (int c = 0; c < 4; ++c) {
                    __half hi = __float2half_rn(vv[c]);
                    __half lo = __float2half_rn(vv[c] - __half2float(hi));
                    uint32_t so = SWZ((uint32_t)((i4 + c) * 128 + krow * 2));
                    *(__half*)((char*)BhiS + so) = hi;
                    *(__half*)((char*)BloS + so) = lo;
                }
            }
            __syncthreads();
#pragma unroll
            for (int ks = 0; ks < 4; ++ks) {
                uint32_t ah[4], al[4];
                uint32_t aoff = SWZ((uint32_t)((mw * 16 + rowA) * 128 + ks * 32 + colA));
                LDSM4(ah, AhiA + aoff);
                LDSM4(al, AloA + aoff);
#pragma unroll
                for (int ntp = 0; ntp < 2; ++ntp) {
                    uint32_t bh[4], bl[4];
                    uint32_t boff = SWZ((uint32_t)((iw * 32 + ntp * 16 + rowB) * 128 + ks * 32 + colB));
                    LDSM4(bh, BhiA + boff);
                    LDSM4(bl, BloA + boff);
                    MMA16816(acc[2 * ntp + 0], ah, bh[0], bh[1]);
                    MMA16816(acc[2 * ntp + 1], ah, bh[2], bh[3]);
                    MMA16816(acc[2 * ntp + 0], al, bh[0], bh[1]);
                    MMA16816(acc[2 * ntp + 1], al, bh[2], bh[3]);
                    MMA16816(acc[2 * ntp + 0], ah, bl[0], bl[1]);
                    MMA16816(acc[2 * ntp + 1], ah, bl[2], bl[3]);
                }
            }
        }

        float alpha = (g == 2) ? 1.0f : 0.5f;
        size_t ibase = (size_t)(s * 4 + mh) * 16384;
        int fl = mw * 16 + (lane >> 2);
#pragma unroll
        for (int nt = 0; nt < 4; ++nt) {
            int i = iw * 32 + nt * 8 + (lane & 3) * 2;
            int n0r = g * 64 + fl;
            __half2 h01 = __floats2half2_rn(acc[nt][0] * alpha, acc[nt][1] * alpha);
            __half2 h23 = __floats2half2_rn(acc[nt][2] * alpha, acc[nt][3] * alpha);
            uint32_t so0 = SWZ((uint32_t)(n0r * 128 + i * 2));
            uint32_t so1 = SWZ((uint32_t)((n0r + 8) * 128 + i * 2));
            *(__half2*)&g_B[ibase + (so0 >> 1)] = h01;
            *(__half2*)&g_B[ibase + (so1 >> 1)] = h23;
        }
    } else {
        int id = (bxid - 128) * 8 + w;  // < 8192
        int s = id >> 10, g = (id >> 8) & 3, m = id & 255;
        const float* W = (g == 0 ? Wi : g == 1 ? Wf : g == 2 ? Wg : Wo)
                         + (size_t)(s * 256 + m) * 512;
        const float* bb = (g == 0 ? bi : g == 1 ? bff : g == 2 ? bg : bo);
        float acc = 0.f;
#pragma unroll
        for (int it = 0; it < 4; ++it) {
            int k0 = it * 128 + lane * 4;
            float4 wv = *(const float4*)&W[k0];
            float4 x = (it < 2) ? *(const float4*)&bx[s * 256 + k0]
                                : *(const float4*)&h0[s * 256 + k0 - 256];
            acc += wv.x * x.x + wv.y * x.y + wv.z * x.z + wv.w * x.w;
        }
#pragma unroll
        for (int d = 16; d > 0; d >>= 1)
            acc += __shfl_xor_sync(0xFFFFFFFFu, acc, d);
        if (lane == 0) {
            float alpha = (g == 2) ? 1.0f : 0.5f;
            g_Bias[id] = alpha * (bb[s * 256 + m] + acc);
        }
    }
}

// ---------------------------------------------------------------------------
// Main kernel: CTA = (128-batch tile, stream). 256 thr, 8 warps (4m x 2f).
// ONE __syncthreads per chunk; prefetch distance 1 (prefetch c+1 issued right
// after the top-of-chunk-c barrier); epilogue + stores run barrier-free.
// SMEM (1024-aligned): bias 4KB | c0 1KB | flags | A 16KB | B0 32KB | B1 32KB
// ---------------------------------------------------------------------------
static constexpr unsigned SMEM_BYTES = 90112 + 1024;

__device__ __forceinline__ void prefetch_B(uint32_t dstA, const __half* slab, int tid) {
#pragma unroll
    for (int j = 0; j < 8; ++j) {
        uint32_t d = dstA + tid * 16 + j * 4096;
        const char* sp = (const char*)slab + tid * 16 + j * 4096;
        asm volatile("cp.async.cg.shared.global [%0], [%1], 16;" :: "r"(d), "l"(sp));
    }
    CPA_COMMIT();
}

__global__ void __launch_bounds__(256, 2)
lnlstm_main(const float* __restrict__ mod, const float* __restrict__ c0g, float* __restrict__ out)
{
    extern __shared__ char dsm[];
    uint32_t sb = smem_u32(dsm);
    uint32_t ab = (sb + 1023u) & ~1023u;
    char* base = dsm + (ab - sb);

    float* bias_s = (float*)base;            // 4KB: [g*256 + cch*64 + f]
    float* c0_s = (float*)(base + 4096);     // 1KB
    int* c0nz = (int*)(base + 5120);         // 4 flags
    char* Ap = base + 8192;                  // 16KB: [128 rows][128B]
    const uint32_t Aa = ab + 8192;
    const uint32_t Ba0 = Aa + 16384, Ba1 = Ba0 + 32768;

    int tid = threadIdx.x;
    int lane = tid & 31, w = tid >> 5;
    int bx = blockIdx.x;
    int s = bx >> 7, b = bx & 127;
    int n0 = b * 128;
    int mbase = (w >> 1) * 32;
    int fbase = (w & 1) * 32;

    const __half* slab = g_B + (size_t)s * 4 * 16384;
    prefetch_B(Ba0, slab, tid);              // chunk 0 only (distance-1 pipeline)

    if (tid < 4) c0nz[tid] = 0;
#pragma unroll
    for (int j = 0; j < 4; ++j) bias_s[tid + 256 * j] = g_Bias[s * 1024 + tid + 256 * j];
    {
        float cv = c0g[s * 256 + tid];
        c0_s[tid] = cv;
        if (cv != 0.0f) atomicOr(&c0nz[tid >> 6], 1);
    }

    // --- A tile: fp32 mod -> fp16, swizzled store (128 rows x 64 cols) ---
    {
        const float* mp = mod + (size_t)n0 * 512 + s * 64;
#pragma unroll
        for (int j = 0; j < 8; ++j) {
            int idx = tid + 256 * j;
            int r = idx >> 4, q = idx & 15;
            float4 v = *(const float4*)(mp + (size_t)r * 512 + q * 4);
            __half2 h01 = __floats2half2_rn(v.x, v.y);
            __half2 h23 = __floats2half2_rn(v.z, v.w);
            uint2 pk;
            pk.x = *(uint32_t*)&h01;
            pk.y = *(uint32_t*)&h23;
            uint32_t so = SWZ((uint32_t)(r * 128 + q * 8));
            *(uint2*)(Ap + so) = pk;
        }
    }
    __syncthreads();                          // A tile + bias/c0/flags ready

    const int rowA = lane & 15;
    const int colA = (lane >> 4) * 16;
    const int rowB = (lane & 7) + ((lane >> 4) << 3);
    const int colB = ((lane >> 3) & 1) * 16;

    // --- preload ALL A fragments (reused across chunks AND gates) ---
    uint32_t afr[4][2][4];
#pragma unroll
    for (int ks = 0; ks < 4; ++ks)
#pragma unroll
        for (int mt = 0; mt < 2; ++mt) {
            uint32_t addr = Aa + SWZ((uint32_t)((mbase + mt * 16 + rowA) * 128 + ks * 32 + colA));
            LDSM4(afr[ks][mt], addr);
        }

#pragma unroll
    for (int cch = 0; cch < 4; ++cch) {
        // Single barrier per chunk.  After it: (a) chunk-c data is visible to
        // every warp, (b) every warp has finished chunk c-1 entirely, so the
        // other buffer is reusable and we immediately prefetch chunk c+1.
        asm volatile("cp.async.wait_group 0;" ::: "memory");
        __syncthreads();
        if (cch < 3)
            prefetch_B((cch & 1) ? Ba0 : Ba1, slab + (cch + 1) * 16384, tid);

        const uint32_t Bcur = (cch & 1) ? Ba1 : Ba0;
        const int fgate_on = c0nz[cch];

        float P[2][4][4];
        float* orow0 = out + (size_t)(n0 + mbase + (lane >> 2)) * 2048
                       + s * 256 + cch * 64 + fbase + (lane & 3) * 2;

#pragma unroll
        for (int step = 0; step < 4; ++step) {
            const int gsel = (step == 0) ? 0 : (step == 1) ? 2 : (step == 2) ? 1 : 3;  // i,g,f,o
            if (step == 2 && !fgate_on) continue;      // f*c0 == 0 exactly

            float2 bias2[4];
#pragma unroll
            for (int nt = 0; nt < 4; ++nt)
                bias2[nt] = *(float2*)&bias_s[gsel * 256 + cch * 64 + fbase + nt * 8 + (lane & 3) * 2];

            float acc[2][4][4];
#pragma unroll
            for (int mt = 0; mt < 2; ++mt)
#pragma unroll
                for (int nt = 0; nt < 4; ++nt) {
                    acc[mt][nt][0] = bias2[nt].x; acc[mt][nt][1] = bias2[nt].y;
                    acc[mt][nt][2] = bias2[nt].x; acc[mt][nt][3] = bias2[nt].y;
                }

#pragma unroll
            for (int ks = 0; ks < 4; ++ks) {
#pragma unroll
                for (int ntp = 0; ntp < 2; ++ntp) {
                    uint32_t bfr[4];
                    uint32_t addr = Bcur + SWZ((uint32_t)((gsel * 64 + fbase + ntp * 16 + rowB) * 128 + ks * 32 + colB));
                    LDSM4(bfr, addr);
                    MMA16816(acc[0][2 * ntp + 0], afr[ks][0], bfr[0], bfr[1]);
                    MMA16816(acc[0][2 * ntp + 1], afr[ks][0], bfr[2], bfr[3]);
                    MMA16816(acc[1][2 * ntp + 0], afr[ks][1], bfr[0], bfr[1]);
                    MMA16816(acc[1][2 * ntp + 1], afr[ks][1], bfr[2], bfr[3]);
                }
            }

#pragma unroll
            for (int mt = 0; mt < 2; ++mt) {
#pragma unroll
                for (int nt = 0; nt < 4; ++nt) {
#pragma unroll
                    for (int q = 0; q < 4; ++q) {
                        float tz = tanha(acc[mt][nt][q]);
                        if (step == 0) {
                            P[mt][nt][q] = fmaf(tz, 0.5f, 0.5f);
                        } else if (step == 1) {
                            P[mt][nt][q] *= tz;
                        } else if (step == 2) {
                            float2 c02 = *(float2*)&c0_s[cch * 64 + fbase + nt * 8 + (lane & 3) * 2];
                            float c0v = (q & 1) ? c02.y : c02.x;
                            P[mt][nt][q] = fmaf(fmaf(tz, 0.5f, 0.5f), c0v, P[mt][nt][q]);
                        } else {
                            float so = fmaf(tz, 0.5f, 0.5f);
                            P[mt][nt][q] = so * tanha(P[mt][nt][q]);
                        }
                    }
                }
            }
        }

        // stores run barrier-free; next chunk's barrier provides reuse safety
#pragma unroll
        for (int mt = 0; mt < 2; ++mt) {
#pragma unroll
            for (int nt = 0; nt < 4; ++nt) {
                float* p0 = orow0 + (size_t)(mt * 16) * 2048 + nt * 8;
                *(float2*)p0 = make_float2(P[mt][nt][0], P[mt][nt][1]);
                *(float2*)(p0 + (size_t)8 * 2048) = make_float2(P[mt][nt][2], P[mt][nt][3]);
            }
        }
    }
}

// ---------------------------------------------------------------------------
extern "C" void kernel_launch(void* const* d_in, const int* in_sizes, int n_in,
                              void* d_out, int out_size)
{
    const float* mod = (const float*)d_in[0];
    const float* h0  = (const float*)d_in[1];
    const float* c0  = (const float*)d_in[2];
    const float* Wx  = (const float*)d_in[3];
    const float* bxp = (const float*)d_in[4];
    const float* Wi  = (const float*)d_in[5];
    const float* bi  = (const float*)d_in[6];
    const float* Wf  = (const float*)d_in[7];
    const float* bfp = (const float*)d_in[8];
    const float* Wg  = (const float*)d_in[9];
    const float* bg  = (const float*)d_in[10];
    const float* Wo  = (const float*)d_in[11];
    const float* bo  = (const float*)d_in[12];
    float* out = (float*)d_out;

    cudaFuncSetAttribute(lnlstm_main, cudaFuncAttributeMaxDynamicSharedMemorySize, SMEM_BYTES);

    lnlstm_pre<<<1152, 256>>>(Wx, Wi, Wf, Wg, Wo, bi, bfp, bg, bo, bxp, h0);
    lnlstm_main<<<1024, 256, SMEM_BYTES>>>(mod, c0, out);
}

// round 13
// speedup vs baseline: 1.1661x; 1.0302x over previous
#include <cuda_runtime.h>
#include <cuda_fp16.h>
#include <cstdint>

// ---------------------------------------------------------------------------
// S=8 streams, I=64 mod dims, M=256 features, N=16384 batch.
// Collapsed math:  z_g[n,s,m] = sum_i C_g[s,m,i]*mod[n,s,i] + Bias[s,g,m]
//   C_g  = alpha_g * (W_g[:, :M] @ Wx),  Bias = alpha_g*(b_g + W_g[:,:M]@bx + W_g[:,M:]@h0)
//   alpha = 0.5 (sigmoid gates i,f,o; sigma(z)=0.5*tanh(z/2)+0.5), 1.0 (tanh gate g)
// Composition on tensor cores with 3-term fp16 hi/lo split (error ~2^-21).
// Main kernel: 8 warps (4m x 2f), A fragments register-resident, 4 feature
// chunks with double-buffered cp.async, ONE __syncthreads per chunk.
// PDL: pre triggers launch_dependents at entry; main overlaps its mod/A-tile
// prologue with pre's tail, then griddepcontrol.wait gates pre-output reads.
// f-gate skipped per chunk when its c0 chunk is all zero (exact).
// ---------------------------------------------------------------------------

// Composed weights, fp16, PRE-SWIZZLED (exact SW128 SMEM image).
// [s][chunk] slab: 256 rows (n = gate*64 + f) x 64 fp16 K-cols (128B rows).
__device__ __align__(16) __half g_B[8 * 4 * 16384];
__device__ float g_Bias[8192];  // [(s*4+g)*256 + m], alpha-folded, g: 0=i,1=f,2=g,3=o

__device__ __forceinline__ uint32_t smem_u32(const void* p) {
    uint32_t a;
    asm("{ .reg .u64 t; cvta.to.shared.u64 t, %1; cvt.u32.u64 %0, t; }" : "=r"(a) : "l"(p));
    return a;
}
__device__ __forceinline__ float tanha(float x) {
    float y; asm("tanh.approx.f32 %0, %1;" : "=f"(y) : "f"(x)); return y;
}

#define SWZ(off) ((off) ^ (((off) >> 3) & 0x70))

#define LDSM4(r, addr)                                                          \
    asm volatile("ldmatrix.sync.aligned.m8n8.x4.shared.b16 {%0,%1,%2,%3}, [%4];" \
        : "=r"((r)[0]), "=r"((r)[1]), "=r"((r)[2]), "=r"((r)[3]) : "r"(addr))

#define MMA16816(d, a, b0, b1)                                                  \
    asm volatile("mma.sync.aligned.m16n8k16.row.col.f32.f16.f16.f32 "           \
        "{%0,%1,%2,%3}, {%4,%5,%6,%7}, {%8,%9}, {%0,%1,%2,%3};"                 \
        : "+f"((d)[0]), "+f"((d)[1]), "+f"((d)[2]), "+f"((d)[3])                \
        : "r"((a)[0]), "r"((a)[1]), "r"((a)[2]), "r"((a)[3]), "r"(b0), "r"(b1))

#define CPA_COMMIT() asm volatile("cp.async.commit_group;" ::: "memory")

// ---------------------------------------------------------------------------
// Precompute.  Blocks [0,128): tensor-core composition, one per (s,g,chunk):
// C tile 64m x 64i, K=256 staged in 4 k64 slices, 3-term fp16 hi/lo split.
// Blocks [128,1152): biases, 8 warps each (one warp per output).
// ---------------------------------------------------------------------------
__global__ void __launch_bounds__(256) lnlstm_pre(
    const float* __restrict__ Wx,
    const float* __restrict__ Wi, const float* __restrict__ Wf,
    const float* __restrict__ Wg, const float* __restrict__ Wo,
    const float* __restrict__ bi, const float* __restrict__ bff,
    const float* __restrict__ bg, const float* __restrict__ bo,
    const float* __restrict__ bx, const float* __restrict__ h0)
{
    // PDL: dependents may launch once every pre block has reached this point.
    asm volatile("griddepcontrol.launch_dependents;" ::: "memory");

    __shared__ __align__(16) __half Ahi[4096], Alo[4096], BhiS[4096], BloS[4096];
    int bxid = blockIdx.x;
    int t = threadIdx.x;
    int lane = t & 31, w = t >> 5;

    if (bxid < 128) {
        int s = bxid >> 4, g = (bxid >> 2) & 3, mh = bxid & 3;   // mh == feature chunk
        const float* Wgate = (g == 0 ? Wi : g == 1 ? Wf : g == 2 ? Wg : Wo);
        const uint32_t AhiA = smem_u32(Ahi), AloA = smem_u32(Alo);
        const uint32_t BhiA = smem_u32(BhiS), BloA = smem_u32(BloS);

        int mw = w >> 1, iw = w & 1;                 // warp tile: 16m x 32i
        const int rowA = lane & 15, colA = (lane >> 4) * 16;
        const int rowB = (lane & 7) + ((lane >> 4) << 3), colB = ((lane >> 3) & 1) * 16;

        float acc[4][4];
#pragma unroll
        for (int nt = 0; nt < 4; ++nt)
#pragma unroll
            for (int q = 0; q < 4; ++q) acc[nt][q] = 0.f;

        for (int kt = 0; kt < 4; ++kt) {
            __syncthreads();
#pragma unroll
            for (int j = 0; j < 4; ++j) {
                int idx = t + 256 * j;
                int row = idx >> 4, c4 = (idx & 15) * 4;
                float4 v = *(const float4*)&Wgate[(size_t)(s * 256 + mh * 64 + row) * 512 + kt * 64 + c4];
                __half hx = __float2half_rn(v.x), hy = __float2half_rn(v.y);
                __half hz = __float2half_rn(v.z), hw = __float2half_rn(v.w);
                __half2 hiA = __halves2half2(hx, hy), hiB = __halves2half2(hz, hw);
                __half2 loA = __floats2half2_rn(v.x - __half2float(hx), v.y - __half2float(hy));
                __half2 loB = __floats2half2_rn(v.z - __half2float(hz), v.w - __half2float(hw));
                uint32_t o0 = SWZ((uint32_t)(row * 128 + c4 * 2));
                uint32_t o1 = SWZ((uint32_t)(row * 128 + c4 * 2 + 4));
                *(__half2*)((char*)Ahi + o0) = hiA;  *(__half2*)((char*)Ahi + o1) = hiB;
                *(__half2*)((char*)Alo + o0) = loA;  *(__half2*)((char*)Alo + o1) = loB;
            }
#pragma unroll
            for (int j = 0; j < 4; ++j) {
                int idx = t + 256 * j;
                int krow = idx >> 4, i4 = (idx & 15) * 4;
                float4 v = *(const float4*)&Wx[(size_t)(s * 256 + kt * 64 + krow) * 64 + i4];
                float vv[4] = {v.x, v.y, v.z, v.w};
#pragma unroll
                for (int c = 0; c < 4; ++c) {
                    __half hi = __float2half_rn(vv[c]);
                    __half lo = __float2half_rn(vv[c] - __half2float(hi));
                    uint32_t so = SWZ((uint32_t)((i4 + c) * 128 + krow * 2));
                    *(__half*)((char*)BhiS + so) = hi;
                    *(__half*)((char*)BloS + so) = lo;
                }
            }
            __syncthreads();
#pragma unroll
            for (int ks = 0; ks < 4; ++ks) {
                uint32_t ah[4], al[4];
                uint32_t aoff = SWZ((uint32_t)((mw * 16 + rowA) * 128 + ks * 32 + colA));
                LDSM4(ah, AhiA + aoff);
                LDSM4(al, AloA + aoff);
#pragma unroll
                for (int ntp = 0; ntp < 2; ++ntp) {
                    uint32_t bh[4], bl[4];
                    uint32_t boff = SWZ((uint32_t)((iw * 32 + ntp * 16 + rowB) * 128 + ks * 32 + colB));
                    LDSM4(bh, BhiA + boff);
                    LDSM4(bl, BloA + boff);
                    MMA16816(acc[2 * ntp + 0], ah, bh[0], bh[1]);
                    MMA16816(acc[2 * ntp + 1], ah, bh[2], bh[3]);
                    MMA16816(acc[2 * ntp + 0], al, bh[0], bh[1]);
                    MMA16816(acc[2 * ntp + 1], al, bh[2], bh[3]);
                    MMA16816(acc[2 * ntp + 0], ah, bl[0], bl[1]);
                    MMA16816(acc[2 * ntp + 1], ah, bl[2], bl[3]);
                }
            }
        }

        float alpha = (g == 2) ? 1.0f : 0.5f;
        size_t ibase = (size_t)(s * 4 + mh) * 16384;
        int fl = mw * 16 + (lane >> 2);
#pragma unroll
        for (int nt = 0; nt < 4; ++nt) {
            int i = iw * 32 + nt * 8 + (lane & 3) * 2;
            int n0r = g * 64 + fl;
            __half2 h01 = __floats2half2_rn(acc[nt][0] * alpha, acc[nt][1] * alpha);
            __half2 h23 = __floats2half2_rn(acc[nt][2] * alpha, acc[nt][3] * alpha);
            uint32_t so0 = SWZ((uint32_t)(n0r * 128 + i * 2));
            uint32_t so1 = SWZ((uint32_t)((n0r + 8) * 128 + i * 2));
            *(__half2*)&g_B[ibase + (so0 >> 1)] = h01;
            *(__half2*)&g_B[ibase + (so1 >> 1)] = h23;
        }
    } else {
        int id = (bxid - 128) * 8 + w;  // < 8192
        int s = id >> 10, g = (id >> 8) & 3, m = id & 255;
        const float* W = (g == 0 ? Wi : g == 1 ? Wf : g == 2 ? Wg : Wo)
                         + (size_t)(s * 256 + m) * 512;
        const float* bb = (g == 0 ? bi : g == 1 ? bff : g == 2 ? bg : bo);
        float acc = 0.f;
#pragma unroll
        for (int it = 0; it < 4; ++it) {
            int k0 = it * 128 + lane * 4;
            float4 wv = *(const float4*)&W[k0];
            float4 x = (it < 2) ? *(const float4*)&bx[s * 256 + k0]
                                : *(const float4*)&h0[s * 256 + k0 - 256];
            acc += wv.x * x.x + wv.y * x.y + wv.z * x.z + wv.w * x.w;
        }
#pragma unroll
        for (int d = 16; d > 0; d >>= 1)
            acc += __shfl_xor_sync(0xFFFFFFFFu, acc, d);
        if (lane == 0) {
            float alpha = (g == 2) ? 1.0f : 0.5f;
            g_Bias[id] = alpha * (bb[s * 256 + m] + acc);
        }
    }
}

// ---------------------------------------------------------------------------
// Main kernel: CTA = (128-batch tile, stream). 256 thr, 8 warps (4m x 2f).
// Prologue (mod A-tile + afr preload) runs BEFORE griddepcontrol.wait so it
// overlaps pre's tail under PDL.  One __syncthreads per chunk; prefetch
// distance 1; epilogue + stores barrier-free.
// SMEM (1024-aligned): bias 4KB | c0 1KB | flags | A 16KB | B0 32KB | B1 32KB
// ---------------------------------------------------------------------------
static constexpr unsigned SMEM_BYTES = 90112 + 1024;

__device__ __forceinline__ void prefetch_B(uint32_t dstA, const __half* slab, int tid) {
#pragma unroll
    for (int j = 0; j < 8; ++j) {
        uint32_t d = dstA + tid * 16 + j * 4096;
        const char* sp = (const char*)slab + tid * 16 + j * 4096;
        asm volatile("cp.async.cg.shared.global [%0], [%1], 16;" :: "r"(d), "l"(sp));
    }
    CPA_COMMIT();
}

__global__ void __launch_bounds__(256, 2)
lnlstm_main(const float* __restrict__ mod, const float* __restrict__ c0g, float* __restrict__ out)
{
    extern __shared__ char dsm[];
    uint32_t sb = smem_u32(dsm);
    uint32_t ab = (sb + 1023u) & ~1023u;
    char* base = dsm + (ab - sb);

    float* bias_s = (float*)base;            // 4KB: [g*256 + cch*64 + f]
    float* c0_s = (float*)(base + 4096);     // 1KB
    int* c0nz = (int*)(base + 5120);         // 4 flags
    char* Ap = base + 8192;                  // 16KB: [128 rows][128B]
    const uint32_t Aa = ab + 8192;
    const uint32_t Ba0 = Aa + 16384, Ba1 = Ba0 + 32768;

    int tid = threadIdx.x;
    int lane = tid & 31, w = tid >> 5;
    int bx = blockIdx.x;
    int s = bx >> 7, b = bx & 127;
    int n0 = b * 128;
    int mbase = (w >> 1) * 32;
    int fbase = (w & 1) * 32;

    if (tid < 4) c0nz[tid] = 0;              // zeroed BEFORE the barrier below

    // --- prologue (independent of pre): A tile fp32 -> fp16, swizzled ---
    {
        const float* mp = mod + (size_t)n0 * 512 + s * 64;
#pragma unroll
        for (int j = 0; j < 8; ++j) {
            int idx = tid + 256 * j;
            int r = idx >> 4, q = idx & 15;
            float4 v = *(const float4*)(mp + (size_t)r * 512 + q * 4);
            __half2 h01 = __floats2half2_rn(v.x, v.y);
            __half2 h23 = __floats2half2_rn(v.z, v.w);
            uint2 pk;
            pk.x = *(uint32_t*)&h01;
            pk.y = *(uint32_t*)&h23;
            uint32_t so = SWZ((uint32_t)(r * 128 + q * 8));
            *(uint2*)(Ap + so) = pk;
        }
    }
    __syncthreads();                          // A tile ready, flags zeroed

    const int rowA = lane & 15;
    const int colA = (lane >> 4) * 16;
    const int rowB = (lane & 7) + ((lane >> 4) << 3);
    const int colB = ((lane >> 3) & 1) * 16;

    // --- preload ALL A fragments (reused across chunks AND gates) ---
    uint32_t afr[4][2][4];
#pragma unroll
    for (int ks = 0; ks < 4; ++ks)
#pragma unroll
        for (int mt = 0; mt < 2; ++mt) {
            uint32_t addr = Aa + SWZ((uint32_t)((mbase + mt * 16 + rowA) * 128 + ks * 32 + colA));
            LDSM4(afr[ks][mt], addr);
        }

    // --- PDL gate: pre's g_B / g_Bias now guaranteed complete + visible ---
    asm volatile("griddepcontrol.wait;" ::: "memory");

    const __half* slab = g_B + (size_t)s * 4 * 16384;
    prefetch_B(Ba0, slab, tid);              // chunk 0 (distance-1 pipeline)

#pragma unroll
    for (int j = 0; j < 4; ++j) bias_s[tid + 256 * j] = g_Bias[s * 1024 + tid + 256 * j];
    {
        float cv = c0g[s * 256 + tid];
        c0_s[tid] = cv;
        if (cv != 0.0f) atomicOr(&c0nz[tid >> 6], 1);
    }

#pragma unroll
    for (int cch = 0; cch < 4; ++cch) {
        // Single barrier per chunk.  After it: (a) chunk-c data visible to all
        // warps, (b) all warps done with chunk c-1 (buffer reusable), and for
        // chunk 0 it also publishes bias_s/c0_s/c0nz.
        asm volatile("cp.async.wait_group 0;" ::: "memory");
        __syncthreads();
        if (cch < 3)
            prefetch_B((cch & 1) ? Ba0 : Ba1, slab + (cch + 1) * 16384, tid);

        const uint32_t Bcur = (cch & 1) ? Ba1 : Ba0;
        const int fgate_on = c0nz[cch];

        float P[2][4][4];
        float* orow0 = out + (size_t)(n0 + mbase + (lane >> 2)) * 2048
                       + s * 256 + cch * 64 + fbase + (lane & 3) * 2;

#pragma unroll
        for (int step = 0; step < 4; ++step) {
            const int gsel = (step == 0) ? 0 : (step == 1) ? 2 : (step == 2) ? 1 : 3;  // i,g,f,o
            if (step == 2 && !fgate_on) continue;      // f*c0 == 0 exactly

            float2 bias2[4];
#pragma unroll
            for (int nt = 0; nt < 4; ++nt)
                bias2[nt] = *(float2*)&bias_s[gsel * 256 + cch * 64 + fbase + nt * 8 + (lane & 3) * 2];

            float acc[2][4][4];
#pragma unroll
            for (int mt = 0; mt < 2; ++mt)
#pragma unroll
                for (int nt = 0; nt < 4; ++nt) {
                    acc[mt][nt][0] = bias2[nt].x; acc[mt][nt][1] = bias2[nt].y;
                    acc[mt][nt][2] = bias2[nt].x; acc[mt][nt][3] = bias2[nt].y;
                }

#pragma unroll
            for (int ks = 0; ks < 4; ++ks) {
#pragma unroll
                for (int ntp = 0; ntp < 2; ++ntp) {
                    uint32_t bfr[4];
                    uint32_t addr = Bcur + SWZ((uint32_t)((gsel * 64 + fbase + ntp * 16 + rowB) * 128 + ks * 32 + colB));
                    LDSM4(bfr, addr);
                    MMA16816(acc[0][2 * ntp + 0], afr[ks][0], bfr[0], bfr[1]);
                    MMA16816(acc[0][2 * ntp + 1], afr[ks][0], bfr[2], bfr[3]);
                    MMA16816(acc[1][2 * ntp + 0], afr[ks][1], bfr[0], bfr[1]);
                    MMA16816(acc[1][2 * ntp + 1], afr[ks][1], bfr[2], bfr[3]);
                }
            }

#pragma unroll
            for (int mt = 0; mt < 2; ++mt) {
#pragma unroll
                for (int nt = 0; nt < 4; ++nt) {
#pragma unroll
                    for (int q = 0; q < 4; ++q) {
                        float tz = tanha(acc[mt][nt][q]);
                        if (step == 0) {
                            P[mt][nt][q] = fmaf(tz, 0.5f, 0.5f);
                        } else if (step == 1) {
                            P[mt][nt][q] *= tz;
                        } else if (step == 2) {
                            float2 c02 = *(float2*)&c0_s[cch * 64 + fbase + nt * 8 + (lane & 3) * 2];
                            float c0v = (q & 1) ? c02.y : c02.x;
                            P[mt][nt][q] = fmaf(fmaf(tz, 0.5f, 0.5f), c0v, P[mt][nt][q]);
                        } else {
                            float so = fmaf(tz, 0.5f, 0.5f);
                            P[mt][nt][q] = so * tanha(P[mt][nt][q]);
                        }
                    }
                }
            }
        }

        // stores run barrier-free; next chunk's barrier provides reuse safety
#pragma unroll
        for (int mt = 0; mt < 2; ++mt) {
#pragma unroll
            for (int nt = 0; nt < 4; ++nt) {
                float* p0 = orow0 + (size_t)(mt * 16) * 2048 + nt * 8;
                *(float2*)p0 = make_float2(P[mt][nt][0], P[mt][nt][1]);
                *(float2*)(p0 + (size_t)8 * 2048) = make_float2(P[mt][nt][2], P[mt][nt][3]);
            }
        }
    }
}

// ---------------------------------------------------------------------------
extern "C" void kernel_launch(void* const* d_in, const int* in_sizes, int n_in,
                              void* d_out, int out_size)
{
    const float* mod = (const float*)d_in[0];
    const float* h0  = (const float*)d_in[1];
    const float* c0  = (const float*)d_in[2];
    const float* Wx  = (const float*)d_in[3];
    const float* bxp = (const float*)d_in[4];
    const float* Wi  = (const float*)d_in[5];
    const float* bi  = (const float*)d_in[6];
    const float* Wf  = (const float*)d_in[7];
    const float* bfp = (const float*)d_in[8];
    const float* Wg  = (const float*)d_in[9];
    const float* bg  = (const float*)d_in[10];
    const float* Wo  = (const float*)d_in[11];
    const float* bo  = (const float*)d_in[12];
    float* out = (float*)d_out;

    cudaFuncSetAttribute(lnlstm_main, cudaFuncAttributeMaxDynamicSharedMemorySize, SMEM_BYTES);

    lnlstm_pre<<<1152, 256>>>(Wx, Wi, Wf, Wg, Wo, bi, bfp, bg, bo, bxp, h0);

    // PDL launch of main: overlaps its prologue with pre's tail.
    cudaLaunchConfig_t cfg = {};
    cfg.gridDim = dim3(1024);
    cfg.blockDim = dim3(256);
    cfg.dynamicSmemBytes = SMEM_BYTES;
    cfg.stream = 0;
    cudaLaunchAttribute attr[1];
    attr[0].id = cudaLaunchAttributeProgrammaticStreamSerialization;
    attr[0].val.programmaticStreamSerializationAllowed = 1;
    cfg.attrs = attr;
    cfg.numAttrs = 1;
    cudaLaunchKernelEx(&cfg, lnlstm_main, mod, c0, out);
}